// round 9
// baseline (speedup 1.0000x reference)
#include <cuda_runtime.h>

// Problem constants (B=128, T=512, X=64, H=256)
#define B_     128
#define T_     512
#define X_     64
#define H_     256
#define NGROUP 16
#define GSIZE  8
#define GRID_  (NGROUP * GSIZE)   // 128 CTAs, one per SM
#define NTHR   256                // 8 warps, 2/SMSP
#define SENT   0x7FC00000u        // NaN sentinel

// ---- smem layout (float offsets), parity double-buffered where raced ----
#define OFF_WO   0        // float [256][8]        (2048)
#define OFF_HID  2048     // float [2][320][8]     (5120)
#define OFF_SP   7168     // float [2][256][8]     (4096)
#define OFF_RED  11264    // u64   [2][256][17]    (17408 floats)
#define OFF_REDP 28672    // u64   [2][256]        (1024 floats)
#define OFF_M0   29696    // float [512]
#define OFF_M1   30208    // float [512]
#define SMEM_FLOATS 30720
#define SMEM_BYTES  (SMEM_FLOATS * 4)   // 122880 B

// write-once cross-CTA state, sentinel-initialized each launch
__device__ __align__(16) float g_hbuf[(size_t)T_ * B_ * H_];
__device__ __align__(16) float g_xbuf[(size_t)T_ * B_ * X_];

__global__ void init_kernel() {
    const uint4 s = make_uint4(SENT, SENT, SENT, SENT);
    size_t n1 = (size_t)T_ * B_ * H_ / 4;
    size_t n2 = (size_t)T_ * B_ * X_ / 4;
    uint4* p1 = (uint4*)g_hbuf;
    uint4* p2 = (uint4*)g_xbuf;
    size_t i = (size_t)blockIdx.x * blockDim.x + threadIdx.x;
    size_t st = (size_t)gridDim.x * blockDim.x;
    for (size_t j = i; j < n1; j += st) p1[j] = s;
    for (size_t j = i; j < n2; j += st) p2[j] = s;
}

// ---- packed f32x2 helpers ----
__device__ __forceinline__ unsigned long long pk2(float a, float b) {
    unsigned long long r;
    asm("mov.b64 %0, {%1, %2};" : "=l"(r) : "f"(a), "f"(b));
    return r;
}
__device__ __forceinline__ void fma2(unsigned long long& d,
                                     unsigned long long a, unsigned long long b) {
    asm("fma.rn.f32x2 %0, %1, %2, %0;" : "+l"(d) : "l"(a), "l"(b));
}
__device__ __forceinline__ unsigned long long add2(unsigned long long a,
                                                   unsigned long long b) {
    unsigned long long d;
    asm("add.rn.f32x2 %0, %1, %2;" : "=l"(d) : "l"(a), "l"(b));
    return d;
}
__device__ __forceinline__ float2 up2(unsigned long long v) {
    float2 r;
    asm("mov.b64 {%0, %1}, %2;" : "=f"(r.x), "=f"(r.y) : "l"(v));
    return r;
}

// ---- relaxed GPU-scope atomics: no tearing, no UB, no ordering chains ----
__device__ __forceinline__ unsigned ld_rlx(const float* p) {
    unsigned v;
    asm volatile("ld.relaxed.gpu.global.b32 %0, [%1];" : "=r"(v) : "l"(p) : "memory");
    return v;
}
__device__ __forceinline__ void st_rlx(float* p, float f) {
    asm volatile("st.relaxed.gpu.global.b32 [%0], %1;" :: "l"(p), "f"(f) : "memory");
}

__device__ __forceinline__ float sig_fast(float x) {
    return 1.0f / (1.0f + __expf(-x));
}
__device__ __forceinline__ float tanh_fast(float x) {
    x = fminf(15.0f, fmaxf(-15.0f, x));
    float e = __expf(-2.0f * x);
    return (1.0f - e) / (1.0f + e);
}

__device__ __forceinline__ void tables(int t, int skip, int& gidx, bool& gz,
                                       int& pidx, bool& pz, bool& late) {
    int pg = (t < skip) ? 2 * t : (t - skip);
    gz = pg < skip; gidx = pg - skip; if (gidx < 0) gidx = 0;
    int pp = (t < skip) ? 2 * t + 1 : (t - skip);
    pz = pp < skip; pidx = pp - skip; if (pidx < 0) pidx = 0;
    late = (!pz) && (pidx >= t);
}

extern __shared__ float smem[];

__global__ void __launch_bounds__(NTHR, 1) decoder_kernel(
    const float* __restrict__ h_enc,
    const float* __restrict__ W_ih,
    const float* __restrict__ W_hh,
    const float* __restrict__ b_ih,
    const float* __restrict__ b_hh,
    const float* __restrict__ W_out,
    const float* __restrict__ b_out,
    const int*   __restrict__ mask0,
    const int*   __restrict__ mask1,
    const int*   __restrict__ skipp,
    float*       __restrict__ out)
{
    const int tid  = threadIdx.x;
    const int cta  = blockIdx.x;
    const int rank = cta & 7;
    const int grp  = cta >> 3;
    const int b0   = grp * 8;
    const int k0   = rank * 32;
    const int skip = skipp ? skipp[0] : 4;

    float* Wo  = smem + OFF_WO;
    float* m0s = smem + OFF_M0;
    float* m1s = smem + OFF_M1;
    const unsigned smem_u32 = (unsigned)__cvta_generic_to_shared(smem);

    const int kl = tid & 31;
    const int q  = tid >> 5;

    // ---- register-resident gate weights for k-col (k0+kl) ----
    float whr[32], whz[32], whn[32];
    {
        const float* pr = W_hh + (size_t)(k0 + kl) * H_ + q * 32;
        const float* pz = W_hh + (size_t)(k0 + kl + H_) * H_ + q * 32;
        const float* pn = W_hh + (size_t)(k0 + kl + 2 * H_) * H_ + q * 32;
        #pragma unroll
        for (int i = 0; i < 32; ++i) {
            whr[i] = __ldg(pr + i);
            whz[i] = __ldg(pz + i);
            whn[i] = __ldg(pn + i);
        }
    }
    float wxr[8], wxz[8], wxn[8];
    {
        const float* pr = W_ih + (size_t)(k0 + kl) * X_ + q * 8;
        const float* pz = W_ih + (size_t)(k0 + kl + H_) * X_ + q * 8;
        const float* pn = W_ih + (size_t)(k0 + kl + 2 * H_) * X_ + q * 8;
        #pragma unroll
        for (int j = 0; j < 8; ++j) {
            wxr[j] = __ldg(pr + j);
            wxz[j] = __ldg(pz + j);
            wxn[j] = __ldg(pn + j);
        }
    }
    for (int i = tid; i < H_ * 8; i += NTHR) {          // projection slice
        int kk2 = i >> 3, xl2 = i & 7;
        Wo[i] = W_out[(size_t)(rank * 8 + xl2) * H_ + kk2];
    }
    for (int i = tid; i < T_; i += NTHR) {
        m0s[i] = (float)mask0[i];
        m1s[i] = (float)mask1[i];
    }

    float br = 0.f, bz = 0.f, bnh = 0.f, bni = 0.f;
    {
        int k = k0 + kl;
        br  = b_ih[k] + b_hh[k];
        bz  = b_ih[k + H_] + b_hh[k + H_];
        bnh = b_hh[k + 2 * H_];
        bni = b_ih[k + 2 * H_];
    }
    float bo = 0.f;
    if (tid < 32) bo = b_out[rank * 8 + (tid & 7)];

    const int xl  = tid & 7;
    const int bl2 = (tid >> 3) & 3;
    const int xx  = 8 * q + (kl & 7);     // x staging role
    const int j0  = kl >> 3;

    __syncthreads();

    for (int t = 0; t < T_; ++t) {
        int gidx, pidx; bool gz, pz, late;
        tables(t, skip, gidx, gz, pidx, pz, late);
        const bool usesp = (!pz) && (!late);
        const int  par   = t & 1;

        float* hidp = smem + OFF_HID + par * 2560;
        float* sPp  = smem + OFF_SP  + par * 2048;
        unsigned long long* redu  = (unsigned long long*)(smem + OFF_RED) + par * 4352;
        float*              redf  = smem + OFF_RED + par * 8704;
        unsigned long long* redpu = (unsigned long long*)(smem + OFF_REDP) + par * 256;
        const unsigned hidh = smem_u32 + (OFF_HID + par * 2560 + q * 32 * 8) * 4;
        const unsigned hidx = smem_u32 + (OFF_HID + par * 2560 + (256 + q * 8) * 8) * 4;

        // ---- stage h-part: kk = tid, 8 batch rows, sentinel-poll (relaxed atomics) ----
        const int kk = tid;
        float hv[8], g[8], sp[8];
        if (t == 0) {
            #pragma unroll
            for (int j = 0; j < 8; ++j) {
                hv[j] = __ldg(h_enc + (size_t)(b0 + j) * H_ + kk);
                g[j] = 0.f; sp[j] = 0.f;
            }
        } else {
            const float* hb = g_hbuf + ((size_t)(t - 1) * B_ + b0) * H_ + kk;
            unsigned hu[8];
            #pragma unroll
            for (int j = 0; j < 8; ++j) hu[j] = ld_rlx(hb + j * H_);
            unsigned gu[8], su[8];
            const bool dedup = usesp && !gz && (pidx == gidx);
            if (!gz) {
                const float* gb = g_hbuf + ((size_t)gidx * B_ + b0) * H_ + kk;
                #pragma unroll
                for (int j = 0; j < 8; ++j) gu[j] = ld_rlx(gb + j * H_);
            }
            if (usesp && !dedup) {
                const float* sb = g_hbuf + ((size_t)pidx * B_ + b0) * H_ + kk;
                #pragma unroll
                for (int j = 0; j < 8; ++j) su[j] = ld_rlx(sb + j * H_);
            }
            #pragma unroll
            for (int j = 0; j < 8; ++j) {
                while (hu[j] == SENT) hu[j] = ld_rlx(hb + j * H_);
                hv[j] = __uint_as_float(hu[j]);
            }
            if (!gz) {
                const float* gb = g_hbuf + ((size_t)gidx * B_ + b0) * H_ + kk;
                #pragma unroll
                for (int j = 0; j < 8; ++j) {
                    while (gu[j] == SENT) gu[j] = ld_rlx(gb + j * H_);
                    g[j] = __uint_as_float(gu[j]);
                }
            } else {
                #pragma unroll
                for (int j = 0; j < 8; ++j) g[j] = 0.f;
            }
            if (usesp) {
                if (dedup) {
                    #pragma unroll
                    for (int j = 0; j < 8; ++j) sp[j] = g[j];
                } else {
                    const float* sb = g_hbuf + ((size_t)pidx * B_ + b0) * H_ + kk;
                    #pragma unroll
                    for (int j = 0; j < 8; ++j) {
                        while (su[j] == SENT) su[j] = ld_rlx(sb + j * H_);
                        sp[j] = __uint_as_float(su[j]);
                    }
                }
            } else {
                #pragma unroll
                for (int j = 0; j < 8; ++j) sp[j] = 0.f;
            }
        }
        {
            float m0 = m0s[t], m1 = m1s[t];
            *(float4*)(hidp + kk * 8) =
                make_float4(hv[0] * m0 + g[0] * m1, hv[1] * m0 + g[1] * m1,
                            hv[2] * m0 + g[2] * m1, hv[3] * m0 + g[3] * m1);
            *(float4*)(hidp + kk * 8 + 4) =
                make_float4(hv[4] * m0 + g[4] * m1, hv[5] * m0 + g[5] * m1,
                            hv[6] * m0 + g[6] * m1, hv[7] * m0 + g[7] * m1);
            *(float4*)(sPp + kk * 8) =
                make_float4(hv[0] + sp[0], hv[1] + sp[1], hv[2] + sp[2], hv[3] + sp[3]);
            *(float4*)(sPp + kk * 8 + 4) =
                make_float4(hv[4] + sp[4], hv[5] + sp[5], hv[6] + sp[6], hv[7] + sp[7]);
        }
        __syncwarp();

        // ---- h-part GEMM (register weights, broadcast LDS operand) ----
        unsigned long long ar[4], az[4], anh[4], ani[4];
        #pragma unroll
        for (int p = 0; p < 4; ++p) { ar[p] = 0; az[p] = 0; anh[p] = 0; ani[p] = 0; }
        #pragma unroll
        for (int i = 0; i < 32; ++i) {
            unsigned long long wr2 = pk2(whr[i], whr[i]);
            unsigned long long wz2 = pk2(whz[i], whz[i]);
            unsigned long long wn2 = pk2(whn[i], whn[i]);
            unsigned long long h01, h23, h45, h67;
            asm("ld.shared.v2.u64 {%0, %1}, [%2];"
                : "=l"(h01), "=l"(h23) : "r"(hidh + i * 32));
            asm("ld.shared.v2.u64 {%0, %1}, [%2];"
                : "=l"(h45), "=l"(h67) : "r"(hidh + i * 32 + 16));
            fma2(ar[0], wr2, h01); fma2(ar[1], wr2, h23);
            fma2(ar[2], wr2, h45); fma2(ar[3], wr2, h67);
            fma2(az[0], wz2, h01); fma2(az[1], wz2, h23);
            fma2(az[2], wz2, h45); fma2(az[3], wz2, h67);
            fma2(anh[0], wn2, h01); fma2(anh[1], wn2, h23);
            fma2(anh[2], wn2, h45); fma2(anh[3], wn2, h67);
        }

        // ---- stage x-part (deferred), then x GEMM ----
        if (t == 0) {
            hidp[(256 + xx) * 8 + j0]     = 0.f;
            hidp[(256 + xx) * 8 + j0 + 4] = 0.f;
        } else {
            const float* xb = g_xbuf + ((size_t)(t - 1) * B_ + b0) * X_ + xx;
            unsigned a = ld_rlx(xb + j0 * X_);
            unsigned b = ld_rlx(xb + (j0 + 4) * X_);
            while (a == SENT) a = ld_rlx(xb + j0 * X_);
            while (b == SENT) b = ld_rlx(xb + (j0 + 4) * X_);
            hidp[(256 + xx) * 8 + j0]     = __uint_as_float(a);
            hidp[(256 + xx) * 8 + j0 + 4] = __uint_as_float(b);
        }
        __syncwarp();
        #pragma unroll
        for (int j = 0; j < 8; ++j) {
            unsigned long long wr2 = pk2(wxr[j], wxr[j]);
            unsigned long long wz2 = pk2(wxz[j], wxz[j]);
            unsigned long long wn2 = pk2(wxn[j], wxn[j]);
            unsigned long long h01, h23, h45, h67;
            asm("ld.shared.v2.u64 {%0, %1}, [%2];"
                : "=l"(h01), "=l"(h23) : "r"(hidx + j * 32));
            asm("ld.shared.v2.u64 {%0, %1}, [%2];"
                : "=l"(h45), "=l"(h67) : "r"(hidx + j * 32 + 16));
            fma2(ar[0], wr2, h01); fma2(ar[1], wr2, h23);
            fma2(ar[2], wr2, h45); fma2(ar[3], wr2, h67);
            fma2(az[0], wz2, h01); fma2(az[1], wz2, h23);
            fma2(az[2], wz2, h45); fma2(az[3], wz2, h67);
            fma2(ani[0], wn2, h01); fma2(ani[1], wn2, h23);
            fma2(ani[2], wn2, h45); fma2(ani[3], wn2, h67);
        }
        {
            unsigned long long* rp = redu + (q * 32 + kl) * 17;
            #pragma unroll
            for (int p = 0; p < 4; ++p) {
                rp[p * 4 + 0] = ar[p];
                rp[p * 4 + 1] = az[p];
                rp[p * 4 + 2] = anh[p];
                rp[p * 4 + 3] = ani[p];
            }
        }

        // ---- projection partials (early case; own warp's seg of sP) ----
        if (!late) {
            unsigned long long acc = 0;
            #pragma unroll 8
            for (int i = 0; i < 32; ++i) {
                int kk2 = q * 32 + i;
                unsigned long long s2 =
                    *(const unsigned long long*)(sPp + kk2 * 8 + 2 * bl2);
                float w = Wo[kk2 * 8 + xl];
                fma2(acc, pk2(w, w), s2);
            }
            redpu[tid] = acc;
        }
        __syncthreads();   // one rendezvous per step

        // ---- finalize h(t) ----
        {
            int bl = q, klf = kl;
            int p = bl >> 1, half = bl & 1;
            float sr = 0.f, sz = 0.f, snh = 0.f, sni = 0.f;
            #pragma unroll
            for (int qq = 0; qq < 8; ++qq) {
                const float* pr = redf + (qq * 32 + klf) * 34 + p * 8 + half;
                sr  += pr[0];
                sz  += pr[2];
                snh += pr[4];
                sni += pr[6];
            }
            float r  = sig_fast(sr + br);
            float z  = sig_fast(sz + bz);
            float n  = tanh_fast(sni + bni + r * (snh + bnh));
            float hvg = hidp[(k0 + klf) * 8 + bl];
            float hn = (1.0f - z) * n + z * hvg;
            st_rlx(g_hbuf + ((size_t)t * B_ + (b0 + bl)) * H_ + (k0 + klf), hn);
        }
        // ---- projection reduce + publish (early case) ----
        if (!late && tid < 32) {
            unsigned long long a2 = 0;
            #pragma unroll
            for (int qq = 0; qq < 8; ++qq) a2 = add2(a2, redpu[qq * 32 + tid]);
            float2 f = up2(a2);
            f.x += bo; f.y += bo;
            int xg = rank * 8 + (tid & 7);
            int bb = (tid >> 3) & 3;
            out[((size_t)(b0 + 2 * bb) * T_ + t) * X_ + xg]     = f.x;
            out[((size_t)(b0 + 2 * bb + 1) * T_ + t) * X_ + xg] = f.y;
            st_rlx(g_xbuf + ((size_t)t * B_ + (b0 + 2 * bb)) * X_ + xg, f.x);
            st_rlx(g_xbuf + ((size_t)t * B_ + (b0 + 2 * bb + 1)) * X_ + xg, f.y);
        }

        // ---- late projection (t == skip-1): needs h(t); poll it ----
        if (late) {
            const float* hb2 = g_hbuf + ((size_t)t * B_ + b0) * H_ + kk;
            unsigned hu2[8];
            #pragma unroll
            for (int j = 0; j < 8; ++j) hu2[j] = ld_rlx(hb2 + j * H_);
            float h2[8];
            #pragma unroll
            for (int j = 0; j < 8; ++j) {
                while (hu2[j] == SENT) hu2[j] = ld_rlx(hb2 + j * H_);
                h2[j] = __uint_as_float(hu2[j]);
            }
            *(float4*)(sPp + kk * 8) =
                make_float4(hv[0] + h2[0], hv[1] + h2[1], hv[2] + h2[2], hv[3] + h2[3]);
            *(float4*)(sPp + kk * 8 + 4) =
                make_float4(hv[4] + h2[4], hv[5] + h2[5], hv[6] + h2[6], hv[7] + h2[7]);
            __syncwarp();
            {
                unsigned long long acc = 0;
                #pragma unroll 8
                for (int i = 0; i < 32; ++i) {
                    int kk2 = q * 32 + i;
                    unsigned long long s2 =
                        *(const unsigned long long*)(sPp + kk2 * 8 + 2 * bl2);
                    float w = Wo[kk2 * 8 + xl];
                    fma2(acc, pk2(w, w), s2);
                }
                redpu[tid] = acc;
            }
            __syncthreads();
            if (tid < 32) {
                unsigned long long a2 = 0;
                #pragma unroll
                for (int qq = 0; qq < 8; ++qq) a2 = add2(a2, redpu[qq * 32 + tid]);
                float2 f = up2(a2);
                f.x += bo; f.y += bo;
                int xg = rank * 8 + (tid & 7);
                int bb = (tid >> 3) & 3;
                out[((size_t)(b0 + 2 * bb) * T_ + t) * X_ + xg]     = f.x;
                out[((size_t)(b0 + 2 * bb + 1) * T_ + t) * X_ + xg] = f.y;
                st_rlx(g_xbuf + ((size_t)t * B_ + (b0 + 2 * bb)) * X_ + xg, f.x);
                st_rlx(g_xbuf + ((size_t)t * B_ + (b0 + 2 * bb + 1)) * X_ + xg, f.y);
            }
        }
        // no trailing barrier — next step's polls provide all ordering
    }
}

extern "C" void kernel_launch(void* const* d_in, const int* in_sizes, int n_in,
                              void* d_out, int out_size) {
    // metadata order: input, h_enc, W_ih, W_hh, b_ih, b_hh, W_out, b_out, mask0, mask1, skip_size
    const float* h_enc = (const float*)d_in[1];
    const float* W_ih  = (const float*)d_in[2];
    const float* W_hh  = (const float*)d_in[3];
    const float* b_ih  = (const float*)d_in[4];
    const float* b_hh  = (const float*)d_in[5];
    const float* W_out = (const float*)d_in[6];
    const float* b_out = (const float*)d_in[7];
    const int*   mask0 = (const int*)d_in[8];
    const int*   mask1 = (const int*)d_in[9];
    const int*   skipp = (n_in > 10) ? (const int*)d_in[10] : (const int*)0;

    cudaFuncSetAttribute(decoder_kernel,
                         cudaFuncAttributeMaxDynamicSharedMemorySize, SMEM_BYTES);
    init_kernel<<<1024, 256>>>();
    decoder_kernel<<<GRID_, NTHR, SMEM_BYTES>>>(
        h_enc, W_ih, W_hh, b_ih, b_hh, W_out, b_out, mask0, mask1, skipp,
        (float*)d_out);
}